// round 2
// baseline (speedup 1.0000x reference)
#include <cuda_runtime.h>
#include <math.h>

#define BATCH 1024
#define TLEN  256
#define UNITS 512
#define FOURU 2048
#define POUT  32

// State buffers (allocation-free: __device__ globals).
__device__ float g_h[2][BATCH * UNITS];
__device__ float g_c[BATCH * UNITS];

// ---------------------------------------------------------------------------
// Zero h[0] and c each launch (kernel_launch must be deterministic).
// ---------------------------------------------------------------------------
__global__ void init_state_kernel() {
    int i = blockIdx.x * blockDim.x + threadIdx.x;
    if (i < BATCH * UNITS) {
        g_h[0][i] = 0.0f;
        g_c[i] = 0.0f;
    }
}

// ---------------------------------------------------------------------------
// One LSTM timestep, fused GEMM + gates + state update.
// Grid: (UNITS/32, BATCH/64) = (16,16). Block: 256 threads.
// CTA tile: 64 batch rows x 32 units, computing all 4 gate columns per unit
// (i.e. a 64 x 128 tile of z = x_t@Wx + h@Wh + b), then c/h update.
// ---------------------------------------------------------------------------
__global__ __launch_bounds__(256) void lstm_step_kernel(
    const float* __restrict__ prices,  // [BATCH, TLEN]
    const float* __restrict__ Wx,      // [1, 4U]
    const float* __restrict__ Wh,      // [U, 4U]
    const float* __restrict__ bias,    // [4U]
    int t, int in_sel)
{
    const float* __restrict__ h_in = g_h[in_sel];
    float* __restrict__ h_out = g_h[in_sel ^ 1];

    __shared__ float As[32][65];   // [k][b], +1 pad: conflict-free
    __shared__ float Bs[32][128];  // [k][g*32 + j]

    const int tid = threadIdx.x;
    const int tx = tid & 15;       // 16 col groups (each: 2 units x 4 gates)
    const int ty = tid >> 4;       // 16 row groups (each: 4 batch rows)
    const int u0 = blockIdx.x * 32;
    const int b0 = blockIdx.y * 64;

    // acc[r][uu][g]
    float acc[4][2][4];

    // Init accumulators with bias + x_t * Wx (rank-1 term).
#pragma unroll
    for (int r = 0; r < 4; r++) {
        const float xv = prices[(b0 + ty * 4 + r) * TLEN + t];
#pragma unroll
        for (int uu = 0; uu < 2; uu++) {
            const int ucol = u0 + tx * 2 + uu;
#pragma unroll
            for (int g = 0; g < 4; g++) {
                const int col = g * UNITS + ucol;
                acc[r][uu][g] = bias[col] + xv * Wx[col];
            }
        }
    }

    // K loop over the 512-wide recurrent contraction.
    for (int k0 = 0; k0 < UNITS; k0 += 32) {
        __syncthreads();
        // Load h tile: 64 rows x 32 k, coalesced, conflict-free stores.
#pragma unroll
        for (int it = 0; it < 8; it++) {
            const int idx = tid + it * 256;
            const int bb = idx >> 5, kk = idx & 31;
            As[kk][bb] = h_in[(b0 + bb) * UNITS + (k0 + kk)];
        }
        // Load Wh tile: 32 k x 128 cols (4 gate groups of 32), coalesced.
#pragma unroll
        for (int it = 0; it < 16; it++) {
            const int idx = tid + it * 256;
            const int kk = idx >> 7, lc = idx & 127;
            const int g = lc >> 5, j = lc & 31;
            Bs[kk][lc] = Wh[(k0 + kk) * FOURU + g * UNITS + (u0 + j)];
        }
        __syncthreads();

#pragma unroll
        for (int kk = 0; kk < 32; kk++) {
            float a[4], bfrag[2][4];
#pragma unroll
            for (int r = 0; r < 4; r++) a[r] = As[kk][ty * 4 + r];
#pragma unroll
            for (int uu = 0; uu < 2; uu++)
#pragma unroll
                for (int g = 0; g < 4; g++)
                    bfrag[uu][g] = Bs[kk][g * 32 + tx * 2 + uu];
#pragma unroll
            for (int r = 0; r < 4; r++)
#pragma unroll
                for (int uu = 0; uu < 2; uu++)
#pragma unroll
                    for (int g = 0; g < 4; g++)
                        acc[r][uu][g] += a[r] * bfrag[uu][g];
        }
    }

    // Gate activations + state update (each (b,u) owned by exactly one thread).
#pragma unroll
    for (int r = 0; r < 4; r++) {
        const int bg = b0 + ty * 4 + r;
#pragma unroll
        for (int uu = 0; uu < 2; uu++) {
            const int ug = u0 + tx * 2 + uu;
            const int idx = bg * UNITS + ug;
            const float iv = 1.0f / (1.0f + expf(-acc[r][uu][0]));
            const float fv = 1.0f / (1.0f + expf(-acc[r][uu][1]));
            const float gv = tanhf(acc[r][uu][2]);
            const float ov = 1.0f / (1.0f + expf(-acc[r][uu][3]));
            const float cn = fv * g_c[idx] + iv * gv;
            g_c[idx] = cn;
            h_out[idx] = ov * tanhf(cn);
        }
    }
}

// ---------------------------------------------------------------------------
// Head: out = relu(h @ Wd + bd) @ Wp + bp.  h is in g_h[0] after 256 steps.
// One thread per batch row. Cheap (<1% of total).
// ---------------------------------------------------------------------------
__global__ __launch_bounds__(256) void head_kernel(
    const float* __restrict__ Wd,  // [U, 64]
    const float* __restrict__ bd,  // [64]
    const float* __restrict__ Wp,  // [64, P]
    const float* __restrict__ bp,  // [P]
    float* __restrict__ out)       // [BATCH, P]
{
    const int b = blockIdx.x * blockDim.x + threadIdx.x;
    if (b >= BATCH) return;
    const float* __restrict__ h = g_h[0];

    float d[64];
#pragma unroll
    for (int j = 0; j < 64; j++) d[j] = bd[j];
    for (int u = 0; u < UNITS; u++) {
        const float hv = h[b * UNITS + u];
        const float* wrow = Wd + u * 64;
#pragma unroll
        for (int j = 0; j < 64; j++) d[j] += hv * wrow[j];
    }
#pragma unroll
    for (int j = 0; j < 64; j++) d[j] = fmaxf(d[j], 0.0f);

#pragma unroll
    for (int p = 0; p < POUT; p++) {
        float s = bp[p];
#pragma unroll
        for (int j = 0; j < 64; j++) s += d[j] * Wp[j * POUT + p];
        out[b * POUT + p] = s;
    }
}

// ---------------------------------------------------------------------------
extern "C" void kernel_launch(void* const* d_in, const int* in_sizes, int n_in,
                              void* d_out, int out_size) {
    const float* prices = (const float*)d_in[0];
    const float* Wx     = (const float*)d_in[1];
    const float* Wh     = (const float*)d_in[2];
    const float* bias   = (const float*)d_in[3];
    const float* Wd     = (const float*)d_in[4];
    const float* bd     = (const float*)d_in[5];
    const float* Wp     = (const float*)d_in[6];
    const float* bp     = (const float*)d_in[7];
    float* out = (float*)d_out;

    init_state_kernel<<<(BATCH * UNITS + 255) / 256, 256>>>();

    dim3 grid(UNITS / 32, BATCH / 64);  // (16, 16)
    for (int t = 0; t < TLEN; t++) {
        lstm_step_kernel<<<grid, 256>>>(prices, Wx, Wh, bias, t, t & 1);
    }
    // After t = 255 (odd, in_sel=1), h lives in g_h[0].
    head_kernel<<<(BATCH + 255) / 256, 256>>>(Wd, bd, Wp, bp, out);
}

// round 3
// speedup vs baseline: 1.0523x; 1.0523x over previous
#include <cuda_runtime.h>
#include <math.h>
#include <stdint.h>

#define BATCH 1024
#define TLEN  256
#define UNITS 512
#define FOURU 2048
#define POUT  32

// State buffers (allocation-free: __device__ globals).
__device__ float g_h[2][BATCH * UNITS];
__device__ float g_c[BATCH * UNITS];

// ---------------------------------------------------------------------------
// Packed f32x2 helpers (ptxas never emits FFMA2 from C++; PTX only).
// ---------------------------------------------------------------------------
__device__ __forceinline__ void fma2(uint64_t& d, uint64_t a, uint64_t b) {
    asm("fma.rn.f32x2 %0, %1, %2, %0;" : "+l"(d) : "l"(a), "l"(b));
}
__device__ __forceinline__ uint64_t pack2(float lo, float hi) {
    uint64_t r;
    asm("mov.b64 %0, {%1, %2};" : "=l"(r) : "f"(lo), "f"(hi));
    return r;
}
__device__ __forceinline__ void unpack2(uint64_t v, float& lo, float& hi) {
    asm("mov.b64 {%0, %1}, %2;" : "=f"(lo), "=f"(hi) : "l"(v));
}
__device__ __forceinline__ uint64_t dup2(float v) {
    uint64_t r;
    asm("mov.b64 %0, {%1, %1};" : "=l"(r) : "f"(v));
    return r;
}

__device__ __forceinline__ float fast_sigmoid(float x) {
    return __fdividef(1.0f, 1.0f + __expf(-x));
}
__device__ __forceinline__ float fast_tanh(float x) {
    // tanh(x) = 2/(1+e^{-2x}) - 1 ; exact saturation at +-inf via e^{inf}/e^{-inf}
    return __fdividef(2.0f, 1.0f + __expf(-2.0f * x)) - 1.0f;
}

// ---------------------------------------------------------------------------
// Zero h[0] and c each launch (kernel_launch must be deterministic).
// ---------------------------------------------------------------------------
__global__ void init_state_kernel() {
    int i = blockIdx.x * blockDim.x + threadIdx.x;
    if (i < BATCH * UNITS) {
        g_h[0][i] = 0.0f;
        g_c[i] = 0.0f;
    }
}

// ---------------------------------------------------------------------------
// One LSTM timestep, fused GEMM + gates + state update, packed f32x2 math.
// Grid: (UNITS/32, BATCH/64) = (16,16). Block: 128 threads.
// CTA tile: 64 batch rows x 128 gate-cols (32 units x 4 gates).
// Thread tile: 8 batch rows (4 packed pairs) x 8 cols (2 units x 4 gates).
// ---------------------------------------------------------------------------
__global__ __launch_bounds__(128, 4) void lstm_step_kernel(
    const float* __restrict__ prices,  // [BATCH, TLEN]
    const float* __restrict__ Wx,      // [1, 4U]
    const float* __restrict__ Wh,      // [U, 4U]
    const float* __restrict__ bias,    // [4U]
    int t, int in_sel)
{
    const float* __restrict__ h_in = g_h[in_sel];
    float* __restrict__ h_out = g_h[in_sel ^ 1];

    // h tile, transposed: As[k][b]. Row stride 66 (even -> 8B-aligned pairs).
    __shared__ float As[32][66];
    // Wh tile, value-duplicated: Bs2[k][g*32+j] = (w,w) packed in u64.
    __shared__ __align__(16) uint64_t Bs2[32][128];

    const int tid = threadIdx.x;
    const int tx = tid & 15;        // 16 col groups (2 units x 4 gates each)
    const int ty = tid >> 4;        // 8 row groups (8 batch rows each)
    const int u0 = blockIdx.x * 32;
    const int b0 = blockIdx.y * 64;
    const int rbase = ty * 8;

    // acc[rp][g][uu]: packed pair of batch rows (rbase+2rp, rbase+2rp+1).
    uint64_t acc[4][4][2];

    // Init: bias + x_t * Wx (rank-1 input term; x differs per row half).
#pragma unroll
    for (int rp = 0; rp < 4; rp++) {
        const float x0 = prices[(b0 + rbase + rp * 2 + 0) * TLEN + t];
        const float x1 = prices[(b0 + rbase + rp * 2 + 1) * TLEN + t];
#pragma unroll
        for (int g = 0; g < 4; g++)
#pragma unroll
            for (int uu = 0; uu < 2; uu++) {
                const int col = g * UNITS + u0 + tx * 2 + uu;
                const float bb = bias[col], ww = Wx[col];
                acc[rp][g][uu] = pack2(bb + x0 * ww, bb + x1 * ww);
            }
    }

    // K loop over the 512-wide recurrent contraction, KC = 32.
    for (int k0 = 0; k0 < UNITS; k0 += 32) {
        __syncthreads();
        // Load h tile (64x32 floats) transposed into As. float4 global reads.
#pragma unroll
        for (int it = 0; it < 4; it++) {
            const int idx = tid + it * 128;       // 512 float4 groups
            const int bb = idx >> 3;              // 0..63
            const int k4 = (idx & 7) * 4;         // 0..28
            const float4 v = *(const float4*)&h_in[(b0 + bb) * UNITS + k0 + k4];
            As[k4 + 0][bb] = v.x;
            As[k4 + 1][bb] = v.y;
            As[k4 + 2][bb] = v.z;
            As[k4 + 3][bb] = v.w;
        }
        // Load Wh tile (32x128 floats), duplicate each value into a u64.
#pragma unroll
        for (int it = 0; it < 8; it++) {
            const int idx = tid + it * 128;       // 1024 float4 groups
            const int kk = idx >> 5;              // 0..31
            const int q = idx & 31;
            const int g = q >> 3;
            const int j4 = (q & 7) * 4;
            const float4 v =
                *(const float4*)&Wh[(k0 + kk) * FOURU + g * UNITS + u0 + j4];
            Bs2[kk][g * 32 + j4 + 0] = dup2(v.x);
            Bs2[kk][g * 32 + j4 + 1] = dup2(v.y);
            Bs2[kk][g * 32 + j4 + 2] = dup2(v.z);
            Bs2[kk][g * 32 + j4 + 3] = dup2(v.w);
        }
        __syncthreads();

#pragma unroll
        for (int kk = 0; kk < 32; kk++) {
            uint64_t a[4];
#pragma unroll
            for (int rp = 0; rp < 4; rp++)
                a[rp] = *(const uint64_t*)&As[kk][rbase + rp * 2];
            uint64_t bv[4][2];
#pragma unroll
            for (int g = 0; g < 4; g++) {
                const ulonglong2 bb =
                    *(const ulonglong2*)&Bs2[kk][g * 32 + tx * 2];
                bv[g][0] = bb.x;
                bv[g][1] = bb.y;
            }
#pragma unroll
            for (int rp = 0; rp < 4; rp++)
#pragma unroll
                for (int g = 0; g < 4; g++)
#pragma unroll
                    for (int uu = 0; uu < 2; uu++)
                        fma2(acc[rp][g][uu], a[rp], bv[g][uu]);
        }
    }

    // Gate activations + state update (each (b,u) owned by exactly one thread).
#pragma unroll
    for (int rp = 0; rp < 4; rp++) {
#pragma unroll
        for (int uu = 0; uu < 2; uu++) {
            float iv[2], fv[2], gv[2], ov[2];
            unpack2(acc[rp][0][uu], iv[0], iv[1]);
            unpack2(acc[rp][1][uu], fv[0], fv[1]);
            unpack2(acc[rp][2][uu], gv[0], gv[1]);
            unpack2(acc[rp][3][uu], ov[0], ov[1]);
#pragma unroll
            for (int hf = 0; hf < 2; hf++) {
                const int row = b0 + rbase + rp * 2 + hf;
                const int u = u0 + tx * 2 + uu;
                const int idx = row * UNITS + u;
                const float i_ = fast_sigmoid(iv[hf]);
                const float f_ = fast_sigmoid(fv[hf]);
                const float g_ = fast_tanh(gv[hf]);
                const float o_ = fast_sigmoid(ov[hf]);
                const float cn = f_ * g_c[idx] + i_ * g_;
                g_c[idx] = cn;
                h_out[idx] = o_ * fast_tanh(cn);
            }
        }
    }
}

// ---------------------------------------------------------------------------
// Head: out = relu(h @ Wd + bd) @ Wp + bp.  h is in g_h[0] after 256 steps.
// ---------------------------------------------------------------------------
__global__ __launch_bounds__(256) void head_kernel(
    const float* __restrict__ Wd,  // [U, 64]
    const float* __restrict__ bd,  // [64]
    const float* __restrict__ Wp,  // [64, P]
    const float* __restrict__ bp,  // [P]
    float* __restrict__ out)       // [BATCH, P]
{
    const int b = blockIdx.x * blockDim.x + threadIdx.x;
    if (b >= BATCH) return;
    const float* __restrict__ h = g_h[0];

    float d[64];
#pragma unroll
    for (int j = 0; j < 64; j++) d[j] = bd[j];
    for (int u = 0; u < UNITS; u++) {
        const float hv = h[b * UNITS + u];
        const float* wrow = Wd + u * 64;
#pragma unroll
        for (int j = 0; j < 64; j++) d[j] += hv * wrow[j];
    }
#pragma unroll
    for (int j = 0; j < 64; j++) d[j] = fmaxf(d[j], 0.0f);

#pragma unroll
    for (int p = 0; p < POUT; p++) {
        float s = bp[p];
#pragma unroll
        for (int j = 0; j < 64; j++) s += d[j] * Wp[j * POUT + p];
        out[b * POUT + p] = s;
    }
}

// ---------------------------------------------------------------------------
extern "C" void kernel_launch(void* const* d_in, const int* in_sizes, int n_in,
                              void* d_out, int out_size) {
    const float* prices = (const float*)d_in[0];
    const float* Wx     = (const float*)d_in[1];
    const float* Wh     = (const float*)d_in[2];
    const float* bias   = (const float*)d_in[3];
    const float* Wd     = (const float*)d_in[4];
    const float* bd     = (const float*)d_in[5];
    const float* Wp     = (const float*)d_in[6];
    const float* bp     = (const float*)d_in[7];
    float* out = (float*)d_out;

    init_state_kernel<<<(BATCH * UNITS + 255) / 256, 256>>>();

    dim3 grid(UNITS / 32, BATCH / 64);  // (16, 16) = 256 CTAs
    for (int t = 0; t < TLEN; t++) {
        lstm_step_kernel<<<grid, 128>>>(prices, Wx, Wh, bias, t, t & 1);
    }
    // After t = 255 (odd, in_sel=1), h lives in g_h[0].
    head_kernel<<<(BATCH + 255) / 256, 256>>>(Wd, bd, Wp, bp, out);
}

// round 5
// speedup vs baseline: 1.5995x; 1.5200x over previous
#include <cuda_runtime.h>
#include <math.h>
#include <stdint.h>

#define BATCH 1024
#define TLEN  256
#define UNITS 512
#define FOURU 2048
#define POUT  32

// State buffers, TRANSPOSED layout [unit][batch] (allocation-free globals).
__device__ float g_h[2][UNITS * BATCH];
__device__ float g_c[UNITS * BATCH];

// ---------------------------------------------------------------------------
// Packed f32x2 + cp.async helpers.
// ---------------------------------------------------------------------------
__device__ __forceinline__ void fma2(uint64_t& d, uint64_t a, uint64_t b) {
    asm("fma.rn.f32x2 %0, %1, %2, %0;" : "+l"(d) : "l"(a), "l"(b));
}
__device__ __forceinline__ uint64_t pack2(float lo, float hi) {
    uint64_t r;
    asm("mov.b64 %0, {%1, %2};" : "=l"(r) : "f"(lo), "f"(hi));
    return r;
}
__device__ __forceinline__ void unpack2(uint64_t v, float& lo, float& hi) {
    asm("mov.b64 {%0, %1}, %2;" : "=f"(lo), "=f"(hi) : "l"(v));
}
__device__ __forceinline__ uint64_t dup2(float v) {
    uint64_t r;
    asm("mov.b64 %0, {%1, %1};" : "=l"(r) : "f"(v));
    return r;
}
__device__ __forceinline__ void cp16(uint32_t dst_smem, const float* src) {
    asm volatile("cp.async.cg.shared.global [%0], [%1], 16;"
                 :: "r"(dst_smem), "l"(src));
}
#define CP_COMMIT() asm volatile("cp.async.commit_group;")
#define CP_WAIT0()  asm volatile("cp.async.wait_group 0;" ::: "memory")

__device__ __forceinline__ float fast_sigmoid(float x) {
    return __fdividef(1.0f, 1.0f + __expf(-x));
}
__device__ __forceinline__ float fast_tanh(float x) {
    return __fdividef(2.0f, 1.0f + __expf(-2.0f * x)) - 1.0f;
}

// ---------------------------------------------------------------------------
__global__ void init_state_kernel() {
    int i = blockIdx.x * blockDim.x + threadIdx.x;
    if (i < UNITS * BATCH) {
        g_h[0][i] = 0.0f;
        g_c[i] = 0.0f;
    }
}

// ---------------------------------------------------------------------------
// One LSTM timestep. Grid (16,16)=256 CTAs, 128 threads.
// CTA tile: 64 batch x 32 units (x4 gates = 128 z-cols).
// Thread tile: 8 batch (4 packed pairs) x 8 cols (2 units x 4 gates).
// h/c transposed [u][b] -> cp.async-friendly A tiles, natural batch pairs.
// ---------------------------------------------------------------------------
__global__ __launch_bounds__(128, 2) void lstm_step_kernel(
    const float* __restrict__ prices,  // [BATCH, TLEN]
    const float* __restrict__ Wx,      // [1, 4U]
    const float* __restrict__ Wh,      // [U, 4U]
    const float* __restrict__ bias,    // [4U]
    int t, int in_sel)
{
    const float* __restrict__ h_in = g_h[in_sel];   // [u][b]
    float* __restrict__ h_out = g_h[in_sel ^ 1];    // [u][b]

    __shared__ __align__(16) float As[2][32][64];   // [k][b] (8 KB x2)
    __shared__ __align__(16) float Bs[2][32][128];  // [k][g*32+j] (16 KB x2)

    const int tid = threadIdx.x;
    const int tx = tid & 15;        // 16 col groups (2 units x 4 gates)
    const int ty = tid >> 4;        // 8 row groups (8 batch rows)
    const int u0 = blockIdx.x * 32;
    const int b0 = blockIdx.y * 64;
    const int rbase = ty * 8;

    const uint32_t as_base = (uint32_t)__cvta_generic_to_shared(&As[0][0][0]);
    const uint32_t bs_base = (uint32_t)__cvta_generic_to_shared(&Bs[0][0][0]);

    // Per-thread cp.async source/dest precompute.
    // As: 512 16B-chunks/tile, 4 per thread. row=idx>>4, chunk=idx&15.
    const int a_row = tid >> 4;           // it adds +8 rows per iteration
    const int a_ch4 = (tid & 15) * 4;
    // Bs: 1024 chunks/tile, 8 per thread. row=idx>>5, q=idx&31.
    const int b_row = tid >> 5;           // it adds +4 rows per iteration
    const int b_q = tid & 31;
    const int b_g = b_q >> 3;
    const int b_j4 = (b_q & 7) * 4;

    // acc[rp][g][uu]: packed pair of batch rows (rbase+2rp, +1).
    uint64_t acc[4][4][2];
#pragma unroll
    for (int rp = 0; rp < 4; rp++) {
        const float x0 = prices[(b0 + rbase + rp * 2 + 0) * TLEN + t];
        const float x1 = prices[(b0 + rbase + rp * 2 + 1) * TLEN + t];
#pragma unroll
        for (int g = 0; g < 4; g++)
#pragma unroll
            for (int uu = 0; uu < 2; uu++) {
                const int col = g * UNITS + u0 + tx * 2 + uu;
                const float bb = bias[col], ww = Wx[col];
                acc[rp][g][uu] = pack2(bb + x0 * ww, bb + x1 * ww);
            }
    }

    // --- tile loader (cp.async) ---
    auto load_tile = [&](int tile, int buf) {
        const int k0 = tile * 32;
#pragma unroll
        for (int it = 0; it < 4; it++) {
            const int row = a_row + it * 8;
            cp16(as_base + (uint32_t)(((buf * 32 + row) * 64 + a_ch4) * 4),
                 h_in + (k0 + row) * BATCH + b0 + a_ch4);
        }
#pragma unroll
        for (int it = 0; it < 8; it++) {
            const int row = b_row + it * 4;
            cp16(bs_base + (uint32_t)(((buf * 32 + row) * 128 + b_g * 32 + b_j4) * 4),
                 Wh + (k0 + row) * FOURU + b_g * UNITS + u0 + b_j4);
        }
        CP_COMMIT();
    };

    load_tile(0, 0);

    for (int tile = 0; tile < 16; tile++) {
        CP_WAIT0();
        __syncthreads();
        if (tile < 15) load_tile(tile + 1, (tile + 1) & 1);

        const int buf = tile & 1;
#pragma unroll
        for (int kk = 0; kk < 32; kk++) {
            uint64_t a[4];
            {
                const ulonglong2 a01 = *(const ulonglong2*)&As[buf][kk][rbase];
                const ulonglong2 a23 = *(const ulonglong2*)&As[buf][kk][rbase + 4];
                a[0] = a01.x; a[1] = a01.y; a[2] = a23.x; a[3] = a23.y;
            }
            uint64_t bv[4][2];
#pragma unroll
            for (int g = 0; g < 4; g++) {
                const float2 w = *(const float2*)&Bs[buf][kk][g * 32 + tx * 2];
                bv[g][0] = dup2(w.x);
                bv[g][1] = dup2(w.y);
            }
#pragma unroll
            for (int rp = 0; rp < 4; rp++)
#pragma unroll
                for (int g = 0; g < 4; g++)
#pragma unroll
                    for (int uu = 0; uu < 2; uu++)
                        fma2(acc[rp][g][uu], a[rp], bv[g][uu]);
        }
    }

    // Gate activations + state update. Transposed c/h: [u][b], batch pairs
    // contiguous -> float2 accesses.
#pragma unroll
    for (int rp = 0; rp < 4; rp++) {
        const int bofs = b0 + rbase + rp * 2;
#pragma unroll
        for (int uu = 0; uu < 2; uu++) {
            const int u = u0 + tx * 2 + uu;
            float iv[2], fv[2], gv[2], ov[2];
            unpack2(acc[rp][0][uu], iv[0], iv[1]);
            unpack2(acc[rp][1][uu], fv[0], fv[1]);
            unpack2(acc[rp][2][uu], gv[0], gv[1]);
            unpack2(acc[rp][3][uu], ov[0], ov[1]);

            const float2 cold = *(const float2*)&g_c[u * BATCH + bofs];
            float2 cnew, hnew;
            {
                const float i_ = fast_sigmoid(iv[0]);
                const float f_ = fast_sigmoid(fv[0]);
                const float g_ = fast_tanh(gv[0]);
                const float o_ = fast_sigmoid(ov[0]);
                cnew.x = f_ * cold.x + i_ * g_;
                hnew.x = o_ * fast_tanh(cnew.x);
            }
            {
                const float i_ = fast_sigmoid(iv[1]);
                const float f_ = fast_sigmoid(fv[1]);
                const float g_ = fast_tanh(gv[1]);
                const float o_ = fast_sigmoid(ov[1]);
                cnew.y = f_ * cold.y + i_ * g_;
                hnew.y = o_ * fast_tanh(cnew.y);
            }
            *(float2*)&g_c[u * BATCH + bofs] = cnew;
            *(float2*)&h_out[u * BATCH + bofs] = hnew;
        }
    }
}

// ---------------------------------------------------------------------------
// Head: out = relu(h @ Wd + bd) @ Wp + bp. h in g_h[0], layout [u][b].
// ---------------------------------------------------------------------------
__global__ __launch_bounds__(256) void head_kernel(
    const float* __restrict__ Wd,  // [U, 64]
    const float* __restrict__ bd,  // [64]
    const float* __restrict__ Wp,  // [64, P]
    const float* __restrict__ bp,  // [P]
    float* __restrict__ out)       // [BATCH, P]
{
    const int b = blockIdx.x * blockDim.x + threadIdx.x;
    if (b >= BATCH) return;
    const float* __restrict__ h = g_h[0];

    float d[64];
#pragma unroll
    for (int j = 0; j < 64; j++) d[j] = bd[j];
    for (int u = 0; u < UNITS; u++) {
        const float hv = h[u * BATCH + b];  // coalesced across threads
        const float* wrow = Wd + u * 64;
#pragma unroll
        for (int j = 0; j < 64; j++) d[j] += hv * wrow[j];
    }
#pragma unroll
    for (int j = 0; j < 64; j++) d[j] = fmaxf(d[j], 0.0f);

#pragma unroll
    for (int p = 0; p < POUT; p++) {
        float s = bp[p];
#pragma unroll
        for (int j = 0; j < 64; j++) s += d[j] * Wp[j * POUT + p];
        out[b * POUT + p] = s;
    }
}

// ---------------------------------------------------------------------------
extern "C" void kernel_launch(void* const* d_in, const int* in_sizes, int n_in,
                              void* d_out, int out_size) {
    const float* prices = (const float*)d_in[0];
    const float* Wx     = (const float*)d_in[1];
    const float* Wh     = (const float*)d_in[2];
    const float* bias   = (const float*)d_in[3];
    const float* Wd     = (const float*)d_in[4];
    const float* bd     = (const float*)d_in[5];
    const float* Wp     = (const float*)d_in[6];
    const float* bp     = (const float*)d_in[7];
    float* out = (float*)d_out;

    init_state_kernel<<<(UNITS * BATCH + 255) / 256, 256>>>();

    dim3 grid(UNITS / 32, BATCH / 64);  // (16, 16) = 256 CTAs
    for (int t = 0; t < TLEN; t++) {
        lstm_step_kernel<<<grid, 128>>>(prices, Wx, Wh, bias, t, t & 1);
    }
    // After t = 255 (odd, in_sel=1), h lives in g_h[0].
    head_kernel<<<(BATCH + 255) / 256, 256>>>(Wd, bd, Wp, bp, out);
}

// round 10
// speedup vs baseline: 3.1785x; 1.9872x over previous
#include <cuda_runtime.h>
#include <cuda_bf16.h>
#include <math.h>
#include <stdint.h>

#define BATCH 1024
#define TLEN  256
#define UNITS 512
#define NCOLS 2048      // 4*UNITS, gate-interleaved: n' = u*4+g
#define POUT  32

#define MT 128          // CTA M tile (batch rows)
#define NT 128          // CTA N tile (z cols)
#define KC 64           // K chunk (bf16) = 128 B rows (SW128 atom)
#define NCHUNK 8
#define TILE_BYTES  16384            // 128 rows x 128 B
#define STAGE_BYTES (4 * TILE_BYTES) // A_hi, A_lo, B_hi, B_lo
#define ZP 132                       // padded z row (floats)
#define DYN_SMEM (2 * STAGE_BYTES)   // 128 KB (>= z tile 128*132*4)

// ---------------- device globals (allocation-free scratch) ----------------
__device__ __nv_bfloat16 g_h_hi[2][BATCH * UNITS];  // [b][u]
__device__ __nv_bfloat16 g_h_lo[2][BATCH * UNITS];
__device__ float         g_c[BATCH * UNITS];        // [b][u]
__device__ __nv_bfloat16 g_wT_hi[NCOLS * UNITS];    // [n'][k]
__device__ __nv_bfloat16 g_wT_lo[NCOLS * UNITS];
__device__ float         g_bias_p[NCOLS];
__device__ float         g_wx_p[NCOLS];

// ---------------- PTX helpers ----------------
__device__ __forceinline__ uint32_t smem_u32(const void* p) {
    return (uint32_t)__cvta_generic_to_shared(p);
}
__device__ __forceinline__ void cp16(uint32_t dst, const void* src) {
    asm volatile("cp.async.cg.shared.global [%0], [%1], 16;" :: "r"(dst), "l"(src));
}
#define CP_COMMIT() asm volatile("cp.async.commit_group;")
#define CP_WAIT1()  asm volatile("cp.async.wait_group 1;" ::: "memory")
#define CP_WAIT0()  asm volatile("cp.async.wait_group 0;" ::: "memory")

#define LDSM_X4(r, addr) \
    asm volatile("ldmatrix.sync.aligned.m8n8.x4.shared.b16 {%0,%1,%2,%3}, [%4];" \
        : "=r"((r)[0]), "=r"((r)[1]), "=r"((r)[2]), "=r"((r)[3]) : "r"(addr))

#define MMA16816(d, a, b) \
    asm volatile("mma.sync.aligned.m16n8k16.row.col.f32.bf16.bf16.f32 " \
        "{%0,%1,%2,%3}, {%4,%5,%6,%7}, {%8,%9}, {%0,%1,%2,%3};" \
        : "+f"((d)[0]), "+f"((d)[1]), "+f"((d)[2]), "+f"((d)[3]) \
        : "r"((a)[0]), "r"((a)[1]), "r"((a)[2]), "r"((a)[3]), \
          "r"((b)[0]), "r"((b)[1]))

__device__ __forceinline__ float fast_sigmoid(float x) {
    return __fdividef(1.0f, 1.0f + __expf(-x));
}
__device__ __forceinline__ float fast_tanh(float x) {
    return __fdividef(2.0f, 1.0f + __expf(-2.0f * x)) - 1.0f;
}

// ---------------- prep kernels (once per launch) ----------------
__global__ void init_state_kernel() {
    int i = blockIdx.x * blockDim.x + threadIdx.x;
    if (i < BATCH * UNITS) {
        g_h_hi[0][i] = __float2bfloat16(0.0f);
        g_h_lo[0][i] = __float2bfloat16(0.0f);
        g_c[i] = 0.0f;
    }
}

__global__ void prep_weights_kernel(const float* __restrict__ Wh,
                                    const float* __restrict__ bias,
                                    const float* __restrict__ Wx) {
    int idx = blockIdx.x * blockDim.x + threadIdx.x;
    if (idx >= NCOLS * UNITS) return;
    const int n = idx / UNITS, k = idx % UNITS;
    const int u = n >> 2, g = n & 3;
    const float w = Wh[k * NCOLS + g * UNITS + u];
    const __nv_bfloat16 hi = __float2bfloat16(w);
    const __nv_bfloat16 lo = __float2bfloat16(w - __bfloat162float(hi));
    g_wT_hi[n * UNITS + k] = hi;
    g_wT_lo[n * UNITS + k] = lo;
    if (k == 0) {
        g_bias_p[n] = bias[g * UNITS + u];
        g_wx_p[n]   = Wx[g * UNITS + u];
    }
}

// ---------------- one LSTM timestep (mma.sync bf16x3) ----------------
__global__ __launch_bounds__(256, 1) void lstm_step_mma(
    const float* __restrict__ prices, int t, int in_sel)
{
    extern __shared__ __align__(1024) char dsm[];
    __shared__ float bias_s[NT], wx_s[NT];

    const int tid = threadIdx.x;
    const int lane = tid & 31;
    const int wid = tid >> 5;
    const int wm = wid & 1;        // 2 M warps (64 rows each)
    const int wn = wid >> 1;       // 4 N warps (32 cols each)
    const int n0 = blockIdx.x * NT;
    const int b0 = blockIdx.y * MT;

    const uint32_t smem0 = smem_u32(dsm);

    if (tid < NT) {
        bias_s[tid] = g_bias_p[n0 + tid];
        wx_s[tid]   = g_wx_p[n0 + tid];
    }

    // -------- cp.async loader precompute (4 chunks of 16B per tile/thread) ----
    // tile = 128 rows x 128 B (SW128): dst = row*128 + ((ch*16) ^ ((row&7)<<4))
    uint32_t ldst[4];
    int lrow[4], lch[4];
#pragma unroll
    for (int p = 0; p < 4; p++) {
        const int idx = tid + p * 256;
        lrow[p] = idx >> 3;
        lch[p] = idx & 7;
        ldst[p] = (uint32_t)(lrow[p] * 128 + ((lch[p] * 16) ^ ((lrow[p] & 7) << 4)));
    }
    const __nv_bfloat16* __restrict__ Ahi_g = g_h_hi[in_sel];
    const __nv_bfloat16* __restrict__ Alo_g = g_h_lo[in_sel];

    auto load_chunk = [&](int c) {
        const uint32_t st = smem0 + (uint32_t)(c & 1) * STAGE_BYTES;
        const int koff = c * KC;
#pragma unroll
        for (int p = 0; p < 4; p++) {
            const size_t asrc = (size_t)(b0 + lrow[p]) * UNITS + koff + lch[p] * 8;
            const size_t bsrc = (size_t)(n0 + lrow[p]) * UNITS + koff + lch[p] * 8;
            cp16(st + 0 * TILE_BYTES + ldst[p], Ahi_g + asrc);
            cp16(st + 1 * TILE_BYTES + ldst[p], Alo_g + asrc);
            cp16(st + 2 * TILE_BYTES + ldst[p], g_wT_hi + bsrc);
            cp16(st + 3 * TILE_BYTES + ldst[p], g_wT_lo + bsrc);
        }
        CP_COMMIT();
    };

    // -------- ldmatrix per-lane addressing --------
    // A (.x4): lanes 0-15 -> rows base+lane&15, lanes 16-31 -> same rows, next 16B chunk.
    const int arow = lane & 15;
    const int asel = lane >> 4;
    const uint32_t axor = (uint32_t)((arow & 7) << 4);
    // B (.x4): covers 2 n8 blocks: lanes 0-7 rows0-7 ch0, 8-15 rows0-7 ch1,
    //          16-23 rows8-15 ch0, 24-31 rows8-15 ch1.
    const int brow = (lane & 7) + ((lane >> 4) << 3);
    const int bsel = (lane >> 3) & 1;
    const uint32_t bxor = (uint32_t)((brow & 7) << 4);

    float acc[4][4][4];
#pragma unroll
    for (int mb = 0; mb < 4; mb++)
#pragma unroll
        for (int nb = 0; nb < 4; nb++)
#pragma unroll
            for (int q = 0; q < 4; q++) acc[mb][nb][q] = 0.0f;

    load_chunk(0);

    for (int c = 0; c < NCHUNK; c++) {
        if (c + 1 < NCHUNK) { load_chunk(c + 1); CP_WAIT1(); }
        else                { CP_WAIT0(); }
        __syncthreads();

        const uint32_t st = smem0 + (uint32_t)(c & 1) * STAGE_BYTES;
        const uint32_t tAh = st;
        const uint32_t tAl = st + TILE_BYTES;
        const uint32_t tBh = st + 2 * TILE_BYTES;
        const uint32_t tBl = st + 3 * TILE_BYTES;

#pragma unroll
        for (int k16 = 0; k16 < 4; k16++) {
            const uint32_t aoff = (uint32_t)(((k16 * 2 + asel) * 16) ^ axor);
            const uint32_t boff = (uint32_t)(((k16 * 2 + bsel) * 16) ^ bxor);
            uint32_t ah[4][4], al[4][4], bh[2][4], bl[2][4];
#pragma unroll
            for (int mb = 0; mb < 4; mb++) {
                const uint32_t ra = (uint32_t)((wm * 64 + mb * 16 + arow) * 128) + aoff;
                LDSM_X4(ah[mb], tAh + ra);
                LDSM_X4(al[mb], tAl + ra);
            }
#pragma unroll
            for (int np = 0; np < 2; np++) {
                const uint32_t rb = (uint32_t)((wn * 32 + np * 16 + brow) * 128) + boff;
                LDSM_X4(bh[np], tBh + rb);
                LDSM_X4(bl[np], tBl + rb);
            }
#pragma unroll
            for (int mb = 0; mb < 4; mb++)
#pragma unroll
                for (int nb = 0; nb < 4; nb++) {
                    const uint32_t* bhp = &bh[nb >> 1][(nb & 1) * 2];
                    const uint32_t* blp = &bl[nb >> 1][(nb & 1) * 2];
                    MMA16816(acc[mb][nb], ah[mb], bhp);
                    MMA16816(acc[mb][nb], al[mb], bhp);
                    MMA16816(acc[mb][nb], ah[mb], blp);
                }
        }
        __syncthreads();  // protect smem stage before next overwrite / z reuse
    }

    // -------- dump accumulators to padded f32 z tile in smem --------
    float* zs = (float*)dsm;  // [128][ZP]
    {
        const int rq = lane >> 2, cq = (lane & 3) * 2;
#pragma unroll
        for (int mb = 0; mb < 4; mb++)
#pragma unroll
            for (int nb = 0; nb < 4; nb++) {
                const int row = wm * 64 + mb * 16 + rq;
                const int col = wn * 32 + nb * 8 + cq;
                *(float2*)&zs[row * ZP + col] =
                    make_float2(acc[mb][nb][0], acc[mb][nb][1]);
                *(float2*)&zs[(row + 8) * ZP + col] =
                    make_float2(acc[mb][nb][2], acc[mb][nb][3]);
            }
    }
    __syncthreads();

    // -------- fused gate epilogue --------
    // thread: rows r = (tid>>3) + 32i (i<4), units ul..ul+3, ul = (tid&7)*4.
    __nv_bfloat16* __restrict__ h_out_hi = g_h_hi[in_sel ^ 1];
    __nv_bfloat16* __restrict__ h_out_lo = g_h_lo[in_sel ^ 1];
    const int ul = (tid & 7) * 4;
    const int ucta = n0 >> 2;

#pragma unroll
    for (int i = 0; i < 4; i++) {
        const int r = (tid >> 3) + 32 * i;
        const int b = b0 + r;
        const float x = prices[b * TLEN + t];
        const size_t cbase = (size_t)b * UNITS + ucta + ul;

        float4 cold = *(const float4*)&g_c[cbase];
        float cn[4], hv[4];
#pragma unroll
        for (int j = 0; j < 4; j++) {
            const int col = (ul + j) * 4;
            const float zi = zs[r * ZP + col + 0] + bias_s[col + 0] + x * wx_s[col + 0];
            const float zf = zs[r * ZP + col + 1] + bias_s[col + 1] + x * wx_s[col + 1];
            const float zg = zs[r * ZP + col + 2] + bias_s[col + 2] + x * wx_s[col + 2];
            const float zo = zs[r * ZP + col + 3] + bias_s[col + 3] + x * wx_s[col + 3];
            const float i_ = fast_sigmoid(zi);
            const float f_ = fast_sigmoid(zf);
            const float g_ = fast_tanh(zg);
            const float o_ = fast_sigmoid(zo);
            const float co = (j == 0) ? cold.x : (j == 1) ? cold.y : (j == 2) ? cold.z : cold.w;
            cn[j] = f_ * co + i_ * g_;
            hv[j] = o_ * fast_tanh(cn[j]);
        }
        *(float4*)&g_c[cbase] = make_float4(cn[0], cn[1], cn[2], cn[3]);

        uint32_t hp[2], lp[2];
#pragma unroll
        for (int j = 0; j < 4; j++) {
            const __nv_bfloat16 bh16 = __float2bfloat16(hv[j]);
            const __nv_bfloat16 bl16 = __float2bfloat16(hv[j] - __bfloat162float(bh16));
            const uint32_t rh = (uint32_t)__bfloat16_as_ushort(bh16);
            const uint32_t rl = (uint32_t)__bfloat16_as_ushort(bl16);
            if (j & 1) { hp[j >> 1] |= rh << 16; lp[j >> 1] |= rl << 16; }
            else       { hp[j >> 1] = rh;        lp[j >> 1] = rl; }
        }
        *(uint2*)&h_out_hi[cbase] = make_uint2(hp[0], hp[1]);
        *(uint2*)&h_out_lo[cbase] = make_uint2(lp[0], lp[1]);
    }
}

// ---------------- head: out = relu(h @ Wd + bd) @ Wp + bp ----------------
__global__ __launch_bounds__(256) void head_kernel(
    const float* __restrict__ Wd, const float* __restrict__ bd,
    const float* __restrict__ Wp, const float* __restrict__ bp,
    float* __restrict__ out)
{
    const int b = blockIdx.x * blockDim.x + threadIdx.x;
    if (b >= BATCH) return;

    float d[64];
#pragma unroll
    for (int j = 0; j < 64; j++) d[j] = bd[j];
    for (int u = 0; u < UNITS; u++) {
        const float hv = __bfloat162float(g_h_hi[0][b * UNITS + u]) +
                         __bfloat162float(g_h_lo[0][b * UNITS + u]);
        const float* wrow = Wd + u * 64;
#pragma unroll
        for (int j = 0; j < 64; j++) d[j] += hv * wrow[j];
    }
#pragma unroll
    for (int j = 0; j < 64; j++) d[j] = fmaxf(d[j], 0.0f);

#pragma unroll
    for (int p = 0; p < POUT; p++) {
        float s = bp[p];
#pragma unroll
        for (int j = 0; j < 64; j++) s += d[j] * Wp[j * POUT + p];
        out[b * POUT + p] = s;
    }
}

// ---------------------------------------------------------------------------
extern "C" void kernel_launch(void* const* d_in, const int* in_sizes, int n_in,
                              void* d_out, int out_size) {
    const float* prices = (const float*)d_in[0];
    const float* Wx     = (const float*)d_in[1];
    const float* Wh     = (const float*)d_in[2];
    const float* bias   = (const float*)d_in[3];
    const float* Wd     = (const float*)d_in[4];
    const float* bd     = (const float*)d_in[5];
    const float* Wp     = (const float*)d_in[6];
    const float* bp     = (const float*)d_in[7];
    float* out = (float*)d_out;

    cudaFuncSetAttribute(lstm_step_mma,
                         cudaFuncAttributeMaxDynamicSharedMemorySize, DYN_SMEM);

    init_state_kernel<<<(BATCH * UNITS + 255) / 256, 256>>>();
    prep_weights_kernel<<<(NCOLS * UNITS + 255) / 256, 256>>>(Wh, bias, Wx);

    dim3 grid(NCOLS / NT, BATCH / MT);  // (16, 8) = 128 CTAs
    for (int t = 0; t < TLEN; t++) {
        lstm_step_mma<<<grid, 256, DYN_SMEM>>>(prices, t, t & 1);
    }
    // t=255 reads buf1, writes buf0 -> final h in buf 0.
    head_kernel<<<(BATCH + 255) / 256, 256>>>(Wd, bd, Wp, bp, out);
}